// round 4
// baseline (speedup 1.0000x reference)
#include <cuda_runtime.h>
#include <math.h>

#define TGT 20
#define BATCH 64
#define APAD 12348            // 9408 + 2352 + 588
#define BASE1 9408
#define BASE2 11760
#define NPART 6
#define K1_BLOCK 512
#define K1_NW 16
#define K2_BLOCK 1024
#define K2_NW 32
#define NBLK2 (BATCH * 3)
#define LISTCAP 4096

__device__ unsigned long long g_key[BATCH * APAD];
__device__ float g_bce[BATCH * APAD];
__device__ unsigned long long g_part_best[BATCH][NPART][TGT];
__device__ float g_part_sums[BATCH][NPART][8];
__device__ float g_partials[NBLK2 * 3];
__device__ unsigned g_done = 0;

// ================= K1: stripe matching + BCE + natural-pos losses =================

struct K1Sh {
    unsigned long long key[2352];
    float tb[TGT][4];
    float ta[TGT];
    int   tl[TGT];
    unsigned long long best[TGT];
    float wred[K1_NW][8];
};

template<int F, int ROWS>
__device__ void k1_impl(const float* __restrict__ pred,
                        const float* __restrict__ tbp, const int* __restrict__ tlp,
                        int b, int part, int rowLo, int base, K1Sh& sh)
{
    constexpr int FSQ = F * F;
    constexpr int SA = ROWS * F * 3;
    constexpr float STRIDE = 448.0f / (float)F;
    const int tid = threadIdx.x;

    if (tid < TGT) {
        const float* p = tbp + (size_t)(b * TGT + tid) * 4;
        float x1 = p[0], y1 = p[1], x2 = p[2], y2 = p[3];
        sh.tb[tid][0] = x1; sh.tb[tid][1] = y1; sh.tb[tid][2] = x2; sh.tb[tid][3] = y2;
        sh.ta[tid] = (x2 - x1) * (y2 - y1);
        sh.tl[tid] = tlp[b * TGT + tid];
        sh.best[tid] = 0ull;
    }
    for (int i = tid; i < SA; i += K1_BLOCK) sh.key[i] = 0ull;
    __syncthreads();

    const float* predb = pred + (size_t)b * 24 * FSQ;
    const float half3 = 1.5f * STRIDE;
    const int rowHi = rowLo + ROWS;

    for (int t = 0; t < TGT; t++) {
        float tx1 = sh.tb[t][0], ty1 = sh.tb[t][1];
        float tx2 = sh.tb[t][2], ty2 = sh.tb[t][3];
        float ta = sh.ta[t];
        int c0 = max(0, (int)floorf((tx1 - half3) / STRIDE - 0.5f));
        int c1 = min(F - 1, (int)ceilf((tx2 + half3) / STRIDE - 0.5f));
        int r0 = max(rowLo, (int)floorf((ty1 - half3) / STRIDE - 0.5f));
        int r1 = min(rowHi - 1, (int)ceilf((ty2 + half3) / STRIDE - 0.5f));
        if (c1 < c0 || r1 < r0) continue;
        int w = c1 - c0 + 1, h = r1 - r0 + 1;
        int n = w * h * 3;
        unsigned long long bt = 0ull;
        for (int i = tid; i < n; i += K1_BLOCK) {
            int ci = i / 3, ai = i - 3 * ci;
            int rr = ci / w, cc = ci - rr * w;
            int r = r0 + rr, c = c0 + cc;
            float cx = ((float)c + 0.5f) * STRIDE;
            float cy = ((float)r + 0.5f) * STRIDE;
            float half = (1.0f + 0.25f * (float)ai) * STRIDE;
            float lx = fmaxf(cx - half, tx1), ly = fmaxf(cy - half, ty1);
            float rx = fminf(cx + half, tx2), ry = fminf(cy + half, ty2);
            float iw = rx - lx, ih = ry - ly;
            if (iw > 0.f && ih > 0.f) {
                float I = iw * ih;
                float areaA = (2.f * half) * (2.f * half);
                float U = areaA + ta - I;
                unsigned ib = __float_as_uint(I / (U + 1e-9f));
                int aloc = ((r - rowLo) * F + c) * 3 + ai;
                atomicMax(&sh.key[aloc],
                          ((unsigned long long)ib << 32) | (unsigned long long)(255 - t));
                int ag = (r * F + c) * 3 + ai;
                unsigned long long pk = ((unsigned long long)ib << 32) |
                                        (unsigned long long)(0xffffffffu - (unsigned)ag);
                if (pk > bt) bt = pk;
            }
        }
        #pragma unroll
        for (int off = 16; off; off >>= 1) {
            unsigned long long o = __shfl_down_sync(0xffffffffu, bt, off);
            if (o > bt) bt = o;
        }
        if ((tid & 31) == 0 && bt) atomicMax(&sh.best[t], bt);
    }
    __syncthreads();

    float acc[5] = {0.f, 0.f, 0.f, 0.f, 0.f}; // posBce, ce, sl, cntPos, cntNeg
    for (int i = tid; i < SA; i += K1_BLOCK) {
        unsigned long long key = sh.key[i];
        float iou = __uint_as_float((unsigned)(key >> 32));
        bool pos = iou >= 0.5f;
        bool neg = iou < 0.3f;
        int cl = i / 3, ai = i - 3 * cl;
        int cellG = rowLo * F + cl;
        float x = predb[(ai * 8 + 4) * FSQ + cellG];
        float bce = fmaxf(x, 0.f) - (pos ? x : 0.f) + __logf(1.f + __expf(-fabsf(x)));
        int gi = b * APAD + base + rowLo * F * 3 + i;
        g_bce[gi] = neg ? -bce : bce;
        g_key[gi] = key;
        if (pos) {
            acc[3] += 1.f; acc[0] += bce;
            int t = 255 - (int)(key & 0xffull);
            int rowG = cellG / F, colG = cellG - rowG * F;
            float cx = ((float)colG + 0.5f) * STRIDE;
            float cy = ((float)rowG + 0.5f) * STRIDE;
            const float* pb = predb + cellG;
            int cs = ai * 8;
            float c0v = pb[(cs + 5) * FSQ], c1v = pb[(cs + 6) * FSQ], c2v = pb[(cs + 7) * FSQ];
            float m = fmaxf(c0v, fmaxf(c1v, c2v));
            float lse = m + logf(expf(c0v - m) + expf(c1v - m) + expf(c2v - m));
            int tg = sh.tl[t] - 1;
            float ct = (tg == 0) ? c0v : ((tg == 1) ? c1v : c2v);
            acc[1] += lse - ct;
            float half = (1.0f + 0.25f * (float)ai) * STRIDE;
            float aw = 2.f * half;
            float gx1 = sh.tb[t][0], gy1 = sh.tb[t][1];
            float gx2 = sh.tb[t][2], gy2 = sh.tb[t][3];
            float td[4] = { ((gx1 + gx2) * 0.5f - cx) / aw, ((gy1 + gy2) * 0.5f - cy) / aw,
                            logf((gx2 - gx1) / aw), logf((gy2 - gy1) / aw) };
            #pragma unroll
            for (int j = 0; j < 4; j++) {
                float d = fabsf(pb[(cs + j) * FSQ] - td[j]);
                acc[2] += (d < 1.f) ? 0.5f * d * d : d - 0.5f;
            }
        } else if (neg) acc[4] += 1.f;
    }
    {
        int lane = tid & 31, wid = tid >> 5;
        #pragma unroll
        for (int i2 = 0; i2 < 5; i2++) {
            float xr = acc[i2];
            #pragma unroll
            for (int off = 16; off; off >>= 1) xr += __shfl_xor_sync(0xffffffffu, xr, off);
            if (lane == 0) sh.wred[wid][i2] = xr;
        }
        __syncthreads();
        if (tid < 5) {
            float s = 0.f;
            #pragma unroll
            for (int w2 = 0; w2 < K1_NW; w2++) s += sh.wred[w2][tid];
            g_part_sums[b][part][tid] = s;
        }
    }
    if (tid < TGT) g_part_best[b][part][tid] = sh.best[tid];
}

__global__ __launch_bounds__(K1_BLOCK)
void k1_kernel(const float* __restrict__ p0, const float* __restrict__ p1,
               const float* __restrict__ p2,
               const float* __restrict__ tb, const int* __restrict__ tl)
{
    __shared__ K1Sh sh;
    int b = blockIdx.x, part = blockIdx.y;
    if (part < 4)       k1_impl<56, 14>(p0, tb, tl, b, part, 14 * part, 0,     sh);
    else if (part == 4) k1_impl<28, 28>(p1, tb, tl, b, part, 0,         BASE1, sh);
    else                k1_impl<14, 14>(p2, tb, tl, b, part, 0,         BASE2, sh);
}

// ================= K2: override corrections + mining + finalize =================

struct K2Sh {
    float tb[TGT][4];
    int   tl[TGT];
    unsigned long long best[TGT];
    int fa[TGT]; int ftg[TGT]; int nf;
    float wred[K2_NW][8];
    float out[8];
    unsigned warpTot[K2_NW];
    unsigned warpSE[K2_NW];
    int selBucket; unsigned selAbove;
    float sums[5];
    float corr[5];
    unsigned listCnt;
    int isLast;
};

template<int N>
__device__ __forceinline__ void redN(float* v, K2Sh& sh) {
    int lane = threadIdx.x & 31, wid = threadIdx.x >> 5;
    #pragma unroll
    for (int i = 0; i < N; i++) {
        float x = v[i];
        #pragma unroll
        for (int off = 16; off; off >>= 1) x += __shfl_xor_sync(0xffffffffu, x, off);
        if (lane == 0) sh.wred[wid][i] = x;
    }
    __syncthreads();
    if (threadIdx.x < N) {
        float s = 0.f;
        #pragma unroll
        for (int w = 0; w < K2_NW; w++) s += sh.wred[w][threadIdx.x];
        sh.out[threadIdx.x] = s;
    }
    __syncthreads();
}

template<int NB>
__device__ void selectBucket(unsigned* hist, int kRem, K2Sh& sh) {
    const int tid = threadIdx.x;
    constexpr int CH = (NB >= K2_BLOCK) ? NB / K2_BLOCK : 1;
    int basei = tid * CH;
    unsigned ls = 0;
    if (basei < NB)
        for (int j = 0; j < CH; j++) ls += hist[basei + j];
    int lane = tid & 31, wid = tid >> 5;
    unsigned v = ls;
    #pragma unroll
    for (int off = 1; off < 32; off <<= 1) {
        unsigned w2 = __shfl_down_sync(0xffffffffu, v, off);
        if (lane + off < 32) v += w2;
    }
    if (lane == 0) sh.warpTot[wid] = v;
    __syncthreads();
    if (tid < K2_NW) {
        unsigned wv = sh.warpTot[tid];
        unsigned ws = wv;
        #pragma unroll
        for (int off = 1; off < K2_NW; off <<= 1) {
            unsigned w2 = __shfl_down_sync(0xffffffffu, ws, off);
            if (tid + off < K2_NW) ws += w2;
        }
        sh.warpSE[tid] = ws - wv;
    }
    __syncthreads();
    unsigned SE = sh.warpSE[wid] + (v - ls);
    if (basei < NB && SE < (unsigned)kRem && SE + ls >= (unsigned)kRem) {
        unsigned c = SE;
        for (int j = CH - 1; j >= 0; j--) {
            unsigned hv = hist[basei + j];
            if (c + hv >= (unsigned)kRem) { sh.selBucket = basei + j; sh.selAbove = c; break; }
            c += hv;
        }
    }
    __syncthreads();
}

__global__ __launch_bounds__(K2_BLOCK)
void k2_kernel(const float* __restrict__ p0, const float* __restrict__ p1,
               const float* __restrict__ p2,
               const float* __restrict__ tbp, const int* __restrict__ tlp,
               float* __restrict__ out)
{
    extern __shared__ unsigned char dyn[];
    __shared__ K2Sh sh;
    int b = blockIdx.x, scale = blockIdx.y;
    int F, base, partLo, partHi;
    const float* pred;
    if (scale == 0)      { F = 56; base = 0;     partLo = 0; partHi = 4; pred = p0; }
    else if (scale == 1) { F = 28; base = BASE1; partLo = 4; partHi = 5; pred = p1; }
    else                 { F = 14; base = BASE2; partLo = 5; partHi = 6; pred = p2; }
    const int FSQ = F * F;
    const int A = FSQ * 3;
    const float STRIDE = 448.0f / (float)F;

    float* s_bce   = (float*)dyn;                       // [9408]
    unsigned* hist = (unsigned*)(dyn + 37632);          // [2048]
    float* binsum  = (float*)(dyn + 45824);             // [2048]
    float* list    = (float*)(dyn + 54016);             // [4096]

    const int tid = threadIdx.x;
    if (tid < TGT) {
        const float* p = tbp + (size_t)(b * TGT + tid) * 4;
        sh.tb[tid][0] = p[0]; sh.tb[tid][1] = p[1];
        sh.tb[tid][2] = p[2]; sh.tb[tid][3] = p[3];
        sh.tl[tid] = tlp[b * TGT + tid];
        unsigned long long m = 0ull;
        for (int pp = partLo; pp < partHi; pp++) {
            unsigned long long v = g_part_best[b][pp][tid];
            if (v > m) m = v;
        }
        sh.best[tid] = m;
    }
    if (tid == 0) {
        for (int i = 0; i < 5; i++) {
            float s = 0.f;
            for (int pp = partLo; pp < partHi; pp++) s += g_part_sums[b][pp][i];
            sh.sums[i] = s;
        }
        int nf = 0;
        for (int t = 0; t < TGT; t++) {
            unsigned long long key = sh.best[t];
            int a = key ? (int)(0xffffffffu - (unsigned)(key & 0xffffffffull)) : 0;
            int j = 0;
            for (; j < nf; j++) if (sh.fa[j] == a) break;
            if (j < nf) sh.ftg[j] = t;
            else { sh.fa[nf] = a; sh.ftg[nf] = t; nf++; }
        }
        sh.nf = nf;
        sh.listCnt = 0;
    }
    for (int i = tid; i < 2048; i += K2_BLOCK) { hist[i] = 0; binsum[i] = 0.f; }
    __syncthreads();

    // pass 1: load bce, build coarse hist + per-bin sums
    const float* gb = g_bce + (size_t)b * APAD + base;
    for (int i = tid; i < A; i += K2_BLOCK) {
        float v = gb[i];
        s_bce[i] = v;
        if (v < 0.f) {
            float bce = -v;
            unsigned bk = __float_as_uint(bce) >> 21;
            atomicAdd(&hist[bk], 1u);
            atomicAdd(&binsum[bk], bce);
        }
    }
    __syncthreads();

    // corrections for forced positives (warp 0)
    if (tid < 32) {
        float corr[5] = {0.f, 0.f, 0.f, 0.f, 0.f};
        if (tid < sh.nf) {
            int a = sh.fa[tid];
            int tF = sh.ftg[tid];
            unsigned long long key = g_key[(size_t)b * APAD + base + a];
            float iou = __uint_as_float((unsigned)(key >> 32));
            int t_nat = 255 - (int)(key & 0xffull);
            bool was_pos = iou >= 0.5f;
            float vold = s_bce[a];
            bool was_neg = vold < 0.f;
            float bce_old = fabsf(vold);
            int cl = a / 3, ai = a - 3 * cl;
            const float* predb = pred + (size_t)b * 24 * FSQ;
            float x = predb[(ai * 8 + 4) * FSQ + cl];
            float bce_new = was_pos ? bce_old : (bce_old - x);
            s_bce[a] = bce_new;   // positive: excluded from neg member pass
            if (was_neg) {
                unsigned bk = __float_as_uint(bce_old) >> 21;
                atomicAdd(&hist[bk], 0xffffffffu);
                atomicAdd(&binsum[bk], -bce_old);
                corr[4] -= 1.f;
            }
            corr[0] += bce_new - (was_pos ? bce_old : 0.f);
            corr[3] += was_pos ? 0.f : 1.f;
            const float* pb = predb + cl;
            int cs = ai * 8;
            float c0v = pb[(cs + 5) * FSQ], c1v = pb[(cs + 6) * FSQ], c2v = pb[(cs + 7) * FSQ];
            float m = fmaxf(c0v, fmaxf(c1v, c2v));
            float lse = m + logf(expf(c0v - m) + expf(c1v - m) + expf(c2v - m));
            int rowG = cl / F, colG = cl - rowG * F;
            float cx = ((float)colG + 0.5f) * STRIDE, cy = ((float)rowG + 0.5f) * STRIDE;
            float half = (1.0f + 0.25f * (float)ai) * STRIDE;
            float aw = 2.f * half;
            float dl[4];
            for (int j = 0; j < 4; j++) dl[j] = pb[(cs + j) * FSQ];
            {
                int tg = sh.tl[tF] - 1;
                float ct = (tg == 0) ? c0v : ((tg == 1) ? c1v : c2v);
                corr[1] += lse - ct;
                float gx1 = sh.tb[tF][0], gy1 = sh.tb[tF][1];
                float gx2 = sh.tb[tF][2], gy2 = sh.tb[tF][3];
                float td[4] = { ((gx1 + gx2) * 0.5f - cx) / aw, ((gy1 + gy2) * 0.5f - cy) / aw,
                                logf((gx2 - gx1) / aw), logf((gy2 - gy1) / aw) };
                for (int j = 0; j < 4; j++) {
                    float d = fabsf(dl[j] - td[j]);
                    corr[2] += (d < 1.f) ? 0.5f * d * d : d - 0.5f;
                }
            }
            if (was_pos) {
                int tg = sh.tl[t_nat] - 1;
                float ct = (tg == 0) ? c0v : ((tg == 1) ? c1v : c2v);
                corr[1] -= lse - ct;
                float gx1 = sh.tb[t_nat][0], gy1 = sh.tb[t_nat][1];
                float gx2 = sh.tb[t_nat][2], gy2 = sh.tb[t_nat][3];
                float td[4] = { ((gx1 + gx2) * 0.5f - cx) / aw, ((gy1 + gy2) * 0.5f - cy) / aw,
                                logf((gx2 - gx1) / aw), logf((gy2 - gy1) / aw) };
                for (int j = 0; j < 4; j++) {
                    float d = fabsf(dl[j] - td[j]);
                    corr[2] -= (d < 1.f) ? 0.5f * d * d : d - 0.5f;
                }
            }
        }
        #pragma unroll
        for (int i2 = 0; i2 < 5; i2++) {
            float xr = corr[i2];
            #pragma unroll
            for (int off = 16; off; off >>= 1) xr += __shfl_xor_sync(0xffffffffu, xr, off);
            if (tid == 0) sh.corr[i2] = xr;
        }
    }
    __syncthreads();

    float posBce = sh.sums[0] + sh.corr[0];
    float ceS    = sh.sums[1] + sh.corr[1];
    float slS    = sh.sums[2] + sh.corr[2];
    int np = (int)(sh.sums[3] + sh.corr[3] + 0.5f);
    int nn = (int)(sh.sums[4] + sh.corr[4] + 0.5f);
    int k = min(3 * np, nn);

    float negTop = 0.f;
    if (k > 0) {
        selectBucket<2048>(hist, k, sh);
        int Bq = sh.selBucket;
        int kRem = k - (int)sh.selAbove;

        float sa[1] = {0.f};
        for (int i = tid; i < 2048; i += K2_BLOCK)
            if (i > Bq) sa[0] += binsum[i];
        redN<1>(sa, sh);
        float sumAbove = sh.out[0];

        for (int i = tid; i < A; i += K2_BLOCK) {
            float v = s_bce[i];
            if (v < 0.f) {
                unsigned u = __float_as_uint(-v);
                if ((int)(u >> 21) == Bq) {
                    unsigned idx = atomicAdd(&sh.listCnt, 1u);
                    if (idx < LISTCAP) list[idx] = -v;
                }
            }
        }
        __syncthreads();
        int m = min((int)sh.listCnt, LISTCAP);

        for (int i = tid; i < 2048; i += K2_BLOCK) hist[i] = 0;
        __syncthreads();
        for (int i = tid; i < m; i += K2_BLOCK) {
            unsigned u = __float_as_uint(list[i]);
            atomicAdd(&hist[(u >> 10) & 0x7ff], 1u);
        }
        __syncthreads();
        selectBucket<2048>(hist, kRem, sh);
        int B2q = sh.selBucket;
        int kRem2 = kRem - (int)sh.selAbove;

        for (int i = tid; i < 1024; i += K2_BLOCK) hist[i] = 0;
        __syncthreads();
        for (int i = tid; i < m; i += K2_BLOCK) {
            unsigned u = __float_as_uint(list[i]);
            if (((u >> 10) & 0x7ff) == (unsigned)B2q) atomicAdd(&hist[u & 0x3ff], 1u);
        }
        __syncthreads();
        selectBucket<1024>(hist, kRem2, sh);
        int B3q = sh.selBucket;

        unsigned thr_u = ((unsigned)Bq << 21) | ((unsigned)B2q << 10) | (unsigned)B3q;
        float thr = __uint_as_float(thr_u);
        float sc[2] = {0.f, 0.f};
        for (int i = tid; i < m; i += K2_BLOCK) {
            float v = list[i];
            if (__float_as_uint(v) > thr_u) { sc[0] += v; sc[1] += 1.f; }
        }
        redN<2>(sc, sh);
        negTop = sumAbove + sh.out[0] + (float)(kRem - (int)sh.out[1]) * thr;
    }

    if (tid == 0) {
        float ol = (posBce + negTop) / (float)max(np + k, 1);
        float cl2 = ceS / (float)max(np, 1);
        float ll = slS / (float)max(4 * np, 1);
        float* o = &g_partials[(scale * BATCH + b) * 3];
        o[0] = ol; o[1] = cl2; o[2] = ll;
        __threadfence();
        unsigned r = atomicAdd(&g_done, 1);
        sh.isLast = (r == NBLK2 - 1) ? 1 : 0;
    }
    __syncthreads();
    if (sh.isLast) {
        float v[3] = {0.f, 0.f, 0.f};
        for (int i = tid; i < NBLK2; i += K2_BLOCK) {
            v[0] += g_partials[i * 3 + 0];
            v[1] += g_partials[i * 3 + 1];
            v[2] += g_partials[i * 3 + 2];
        }
        redN<3>(v, sh);
        if (tid == 0) {
            float obj = sh.out[0] / (float)BATCH;
            float cls = sh.out[1] / (float)BATCH;
            float loc = sh.out[2] / (float)BATCH;
            out[0] = obj; out[1] = cls; out[2] = loc;
            out[3] = obj + cls + 2.0f * loc;
            g_done = 0;  // reset for next graph replay
        }
    }
}

extern "C" void kernel_launch(void* const* d_in, const int* in_sizes, int n_in,
                              void* d_out, int out_size)
{
    const float* pred1 = (const float*)d_in[0];
    const float* pred2 = (const float*)d_in[1];
    const float* pred3 = (const float*)d_in[2];
    const float* tb    = (const float*)d_in[6];
    const int*   tl    = (const int*)d_in[7];

    const int smem2 = 37632 + 8192 + 8192 + LISTCAP * 4;  // 70400
    cudaFuncSetAttribute(k2_kernel, cudaFuncAttributeMaxDynamicSharedMemorySize, smem2);

    k1_kernel<<<dim3(BATCH, 6), K1_BLOCK>>>(pred1, pred2, pred3, tb, tl);
    k2_kernel<<<dim3(BATCH, 3), K2_BLOCK, smem2>>>(pred1, pred2, pred3, tb, tl,
                                                   (float*)d_out);
}

// round 6
// speedup vs baseline: 1.9042x; 1.9042x over previous
#include <cuda_runtime.h>
#include <math.h>

#define TGT 20
#define BATCH 64
#define BLOCK 1024
#define NWARP (BLOCK / 32)
#define MAXA 9408
#define NBLK (3 * BATCH)
#define LISTCAP 4096

// dynamic smem layout (bytes)
#define OFF_KEY  0                        // ull[MAXA]   75264
#define OFF_BCE  75264                    // f32[MAXA]   37632  (neg sign-encoded)
#define OFF_OV   112896                   // u8[MAXA]     9408  (override t or 0xff)
#define OFF_HIST 122304                   // u32[2048]    8192
#define OFF_LIST 130496                   // f32[4096]   16384
#define SMEM_BYTES 146880

struct Sh {
    float tb[TGT][4];
    float tarea[TGT];
    int   tlab[TGT];
    unsigned long long best[TGT];
    float wred[NWARP][8];
    float out[8];
    unsigned warpTot[NWARP];
    unsigned warpSE[NWARP];
    int selBucket;
    unsigned selAbove;
    unsigned listCnt;
    int isLast;
};

__device__ float g_partials[NBLK * 3];
__device__ unsigned g_done = 0;

template<int N>
__device__ __forceinline__ void redN(float* v, Sh& sh) {
    int lane = threadIdx.x & 31, wid = threadIdx.x >> 5;
    #pragma unroll
    for (int i = 0; i < N; i++) {
        float x = v[i];
        #pragma unroll
        for (int off = 16; off; off >>= 1) x += __shfl_xor_sync(0xffffffffu, x, off);
        if (lane == 0) sh.wred[wid][i] = x;
    }
    __syncthreads();
    if (threadIdx.x < N) {
        float s = 0.f;
        #pragma unroll
        for (int w = 0; w < NWARP; w++) s += sh.wred[w][threadIdx.x];
        sh.out[threadIdx.x] = s;
    }
    __syncthreads();
}

template<int NB>
__device__ void selectBucket(unsigned* hist, int kRem, Sh& sh) {
    const int tid = threadIdx.x;
    constexpr int CH = (NB >= BLOCK) ? NB / BLOCK : 1;
    int basei = tid * CH;
    unsigned ls = 0;
    if (basei < NB)
        #pragma unroll
        for (int j = 0; j < CH; j++) ls += hist[basei + j];
    int lane = tid & 31, wid = tid >> 5;
    unsigned v = ls;
    #pragma unroll
    for (int off = 1; off < 32; off <<= 1) {
        unsigned w2 = __shfl_down_sync(0xffffffffu, v, off);
        if (lane + off < 32) v += w2;
    }
    if (lane == 0) sh.warpTot[wid] = v;
    __syncthreads();
    if (tid < NWARP) {
        unsigned wv = sh.warpTot[tid];
        unsigned ws = wv;
        #pragma unroll
        for (int off = 1; off < NWARP; off <<= 1) {
            unsigned w2 = __shfl_down_sync(0xffffffffu, ws, off);
            if (tid + off < NWARP) ws += w2;
        }
        sh.warpSE[tid] = ws - wv;
    }
    __syncthreads();
    unsigned SE = sh.warpSE[wid] + (v - ls);
    if (basei < NB && SE < (unsigned)kRem && SE + ls >= (unsigned)kRem) {
        unsigned c = SE;
        #pragma unroll
        for (int j = CH - 1; j >= 0; j--) {
            unsigned hv = hist[basei + j];
            if (c + hv >= (unsigned)kRem) { sh.selBucket = basei + j; sh.selAbove = c; break; }
            c += hv;
        }
    }
    __syncthreads();
}

template<int F>
__device__ void run_scale(const float* __restrict__ pred,
                          const float* __restrict__ tb,
                          const int* __restrict__ tl,
                          float* __restrict__ out,
                          int b, int scale,
                          unsigned char* dyn, Sh& sh)
{
    constexpr int FSQ = F * F;
    constexpr int A = FSQ * 3;
    constexpr float STRIDE = 448.0f / (float)F;

    unsigned long long* s_key = (unsigned long long*)(dyn + OFF_KEY);
    float* s_bce = (float*)(dyn + OFF_BCE);
    unsigned char* s_ov = dyn + OFF_OV;
    unsigned* hist = (unsigned*)(dyn + OFF_HIST);
    float* list = (float*)(dyn + OFF_LIST);

    const int tid = threadIdx.x;
    if (tid < TGT) {
        const float* p = tb + (size_t)(b * TGT + tid) * 4;
        float x1 = p[0], y1 = p[1], x2 = p[2], y2 = p[3];
        sh.tb[tid][0] = x1; sh.tb[tid][1] = y1; sh.tb[tid][2] = x2; sh.tb[tid][3] = y2;
        sh.tarea[tid] = (x2 - x1) * (y2 - y1);
        sh.tlab[tid] = tl[b * TGT + tid];
        sh.best[tid] = 0ull;
    }
    if (tid == 0) sh.listCnt = 0;
    for (int a = tid; a < A; a += BLOCK) { s_key[a] = 0ull; s_ov[a] = 0xff; }
    for (int i = tid; i < 2048; i += BLOCK) hist[i] = 0;
    __syncthreads();

    const float* predb = pred + (size_t)b * 24 * FSQ;

    // ---------- Phase 1: target-centric sparse IoU scatter (cell-major) ----------
    const float half3 = 1.5f * STRIDE;
    for (int t = 0; t < TGT; t++) {
        float tx1 = sh.tb[t][0], ty1 = sh.tb[t][1];
        float tx2 = sh.tb[t][2], ty2 = sh.tb[t][3];
        float ta = sh.tarea[t];
        int c0 = max(0, (int)floorf((tx1 - half3) / STRIDE - 0.5f));
        int c1 = min(F - 1, (int)ceilf((tx2 + half3) / STRIDE - 0.5f));
        int r0 = max(0, (int)floorf((ty1 - half3) / STRIDE - 0.5f));
        int r1 = min(F - 1, (int)ceilf((ty2 + half3) / STRIDE - 0.5f));
        if (c1 < c0 || r1 < r0) continue;
        int w = c1 - c0 + 1, hh = r1 - r0 + 1;
        int n = w * hh;
        unsigned long long bt = 0ull;
        for (int i = tid; i < n; i += BLOCK) {
            int rr = i / w, cc = i - rr * w;
            int r = r0 + rr, c = c0 + cc;
            float cx = ((float)c + 0.5f) * STRIDE;
            float cy = ((float)r + 0.5f) * STRIDE;
            int abase = (r * F + c) * 3;
            #pragma unroll
            for (int ai = 0; ai < 3; ai++) {
                float half = (1.0f + 0.25f * (float)ai) * STRIDE;
                float lx = fmaxf(cx - half, tx1), ly = fmaxf(cy - half, ty1);
                float rx = fminf(cx + half, tx2), ry = fminf(cy + half, ty2);
                float iw = rx - lx, ih = ry - ly;
                if (iw > 0.f && ih > 0.f) {
                    float I = iw * ih;
                    float areaA = (2.f * half) * (2.f * half);
                    float U = areaA + ta - I;
                    unsigned ib = __float_as_uint(I / (U + 1e-9f));
                    int a = abase + ai;
                    atomicMax(&s_key[a],
                        ((unsigned long long)ib << 32) | (unsigned long long)(255 - t));
                    unsigned long long pk = ((unsigned long long)ib << 32) |
                        (unsigned long long)(0xffffffffu - (unsigned)a);
                    if (pk > bt) bt = pk;
                }
            }
        }
        #pragma unroll
        for (int off = 16; off; off >>= 1) {
            unsigned long long o = __shfl_down_sync(0xffffffffu, bt, off);
            if (o > bt) bt = o;
        }
        if ((tid & 31) == 0 && bt) atomicMax(&sh.best[t], bt);
    }
    __syncthreads();

    // ---------- Phase 2: forced-positive override (last target wins) ----------
    if (tid == 0) {
        #pragma unroll
        for (int t = 0; t < TGT; t++) {
            if (sh.best[t]) {
                unsigned a = 0xffffffffu - (unsigned)(sh.best[t] & 0xffffffffull);
                s_ov[a] = (unsigned char)t;
            }
        }
    }
    __syncthreads();

    // ---------- Phase 3: BCE + hist + positive cls/loc losses (fused) ----------
    float acc[5] = {0.f, 0.f, 0.f, 0.f, 0.f}; // posBce, ce, sl, cntPos, cntNeg
    for (int cell = tid; cell < FSQ; cell += BLOCK) {
        int row = cell / F, col = cell - row * F;
        float cx = ((float)col + 0.5f) * STRIDE;
        float cy = ((float)row + 0.5f) * STRIDE;
        #pragma unroll
        for (int ai = 0; ai < 3; ai++) {
            int a = cell * 3 + ai;
            unsigned long long key = s_key[a];
            float iou = __uint_as_float((unsigned)(key >> 32));
            unsigned char ov = s_ov[a];
            bool forced = (ov != 0xff);
            bool pos = forced || (iou >= 0.5f);
            bool neg = (!forced) && (iou < 0.3f);
            float x = predb[(ai * 8 + 4) * FSQ + cell];
            float bce = fmaxf(x, 0.f) - (pos ? x : 0.f) + __logf(1.f + __expf(-fabsf(x)));
            s_bce[a] = neg ? -bce : bce;
            if (neg) {
                atomicAdd(&hist[__float_as_uint(bce) >> 21], 1u);
                acc[4] += 1.f;
            }
            if (pos) {
                acc[3] += 1.f; acc[0] += bce;
                int t = forced ? (int)ov : (255 - (int)(key & 0xffull));
                const float* pb = predb + cell;
                int cs = ai * 8;
                float c0v = pb[(cs + 5) * FSQ], c1v = pb[(cs + 6) * FSQ], c2v = pb[(cs + 7) * FSQ];
                float m = fmaxf(c0v, fmaxf(c1v, c2v));
                float lse = m + logf(expf(c0v - m) + expf(c1v - m) + expf(c2v - m));
                int tg = sh.tlab[t] - 1;
                float ct = (tg == 0) ? c0v : ((tg == 1) ? c1v : c2v);
                acc[1] += lse - ct;
                float half = (1.0f + 0.25f * (float)ai) * STRIDE;
                float aw = 2.f * half;
                float gx1 = sh.tb[t][0], gy1 = sh.tb[t][1];
                float gx2 = sh.tb[t][2], gy2 = sh.tb[t][3];
                float td[4] = { ((gx1 + gx2) * 0.5f - cx) / aw, ((gy1 + gy2) * 0.5f - cy) / aw,
                                logf((gx2 - gx1) / aw), logf((gy2 - gy1) / aw) };
                #pragma unroll
                for (int j = 0; j < 4; j++) {
                    float d = fabsf(pb[(cs + j) * FSQ] - td[j]);
                    acc[2] += (d < 1.f) ? 0.5f * d * d : d - 0.5f;
                }
            }
        }
    }
    redN<5>(acc, sh);
    float rPosBce = sh.out[0], rCe = sh.out[1], rSl = sh.out[2];
    int np = (int)sh.out[3], nn = (int)sh.out[4];
    int k = min(3 * np, nn);

    // ---------- Phase 4: hard-negative mining ----------
    float negTop = 0.f;
    if (k > 0) {
        // level 0: coarse bucket (top 11 bits) over full hist
        selectBucket<2048>(hist, k, sh);
        int Bq = sh.selBucket;
        int kRem = k - (int)sh.selAbove;

        // compact bucket members + accumulate sum of strictly-above buckets
        float sa[1] = {0.f};
        for (int a = tid; a < A; a += BLOCK) {
            float v = s_bce[a];
            if (v < 0.f) {
                float bce = -v;
                int bk = (int)(__float_as_uint(bce) >> 21);
                if (bk > Bq) sa[0] += bce;
                else if (bk == Bq) {
                    unsigned idx = atomicAdd(&sh.listCnt, 1u);
                    if (idx < LISTCAP) list[idx] = bce;
                }
            }
        }
        redN<1>(sa, sh);
        float sumAbove = sh.out[0];
        int m = (int)sh.listCnt;

        if (m <= LISTCAP) {
            // level 1 on list (bits 20..10)
            for (int i = tid; i < 2048; i += BLOCK) hist[i] = 0;
            __syncthreads();
            for (int i = tid; i < m; i += BLOCK)
                atomicAdd(&hist[(__float_as_uint(list[i]) >> 10) & 0x7ff], 1u);
            __syncthreads();
            selectBucket<2048>(hist, kRem, sh);
            int B2q = sh.selBucket;
            int kRem2 = kRem - (int)sh.selAbove;

            // level 2 on list (bits 9..0)
            for (int i = tid; i < 1024; i += BLOCK) hist[i] = 0;
            __syncthreads();
            for (int i = tid; i < m; i += BLOCK) {
                unsigned u = __float_as_uint(list[i]);
                if (((u >> 10) & 0x7ff) == (unsigned)B2q) atomicAdd(&hist[u & 0x3ff], 1u);
            }
            __syncthreads();
            selectBucket<1024>(hist, kRem2, sh);
            unsigned thr_u = ((unsigned)Bq << 21) | ((unsigned)sh.selBucket << 10)
                           | (unsigned)sh.selBucket; // placeholder fix below
            thr_u = ((unsigned)Bq << 21) | ((unsigned)B2q << 10) | (unsigned)sh.selBucket;
            float thr = __uint_as_float(thr_u);

            float sc[2] = {0.f, 0.f};
            for (int i = tid; i < m; i += BLOCK) {
                float v = list[i];
                if (__float_as_uint(v) > thr_u) { sc[0] += v; sc[1] += 1.f; }
            }
            redN<2>(sc, sh);
            negTop = sumAbove + sh.out[0] + (float)(kRem - (int)sh.out[1]) * thr;
        } else {
            // fallback: full-A scans (exact, as in R3)
            for (int i = tid; i < 2048; i += BLOCK) hist[i] = 0;
            __syncthreads();
            for (int a = tid; a < A; a += BLOCK) {
                float v = s_bce[a];
                if (v < 0.f) {
                    unsigned u = __float_as_uint(-v);
                    if ((int)(u >> 21) == Bq) atomicAdd(&hist[(u >> 10) & 0x7ff], 1u);
                }
            }
            __syncthreads();
            selectBucket<2048>(hist, kRem, sh);
            int B2q = sh.selBucket;
            int kRem2 = kRem - (int)sh.selAbove;
            for (int i = tid; i < 1024; i += BLOCK) hist[i] = 0;
            __syncthreads();
            for (int a = tid; a < A; a += BLOCK) {
                float v = s_bce[a];
                if (v < 0.f) {
                    unsigned u = __float_as_uint(-v);
                    if ((int)(u >> 21) == Bq && ((u >> 10) & 0x7ff) == (unsigned)B2q)
                        atomicAdd(&hist[u & 0x3ff], 1u);
                }
            }
            __syncthreads();
            selectBucket<1024>(hist, kRem2, sh);
            unsigned thr_u = ((unsigned)Bq << 21) | ((unsigned)B2q << 10) | (unsigned)sh.selBucket;
            float thr = __uint_as_float(thr_u);
            float sc[2] = {0.f, 0.f};
            for (int a = tid; a < A; a += BLOCK) {
                float v = s_bce[a];
                if (v < 0.f) {
                    unsigned u = __float_as_uint(-v);
                    if (u > thr_u) { sc[0] += -v; sc[1] += 1.f; }
                }
            }
            redN<2>(sc, sh);
            negTop = sh.out[0] + (float)(k - (int)sh.out[1]) * thr;
        }
    }

    // ---------- Phase 5: partials + fused last-block finalize ----------
    if (tid == 0) {
        float ol = (rPosBce + negTop) / (float)max(np + k, 1);
        float cl = rCe / (float)max(np, 1);
        float ll = rSl / (float)max(4 * np, 1);
        float* o = &g_partials[(scale * BATCH + b) * 3];
        o[0] = ol; o[1] = cl; o[2] = ll;
        __threadfence();
        unsigned r = atomicAdd(&g_done, 1);
        sh.isLast = (r == NBLK - 1) ? 1 : 0;
    }
    __syncthreads();
    if (sh.isLast) {
        float v[3] = {0.f, 0.f, 0.f};
        for (int i = tid; i < NBLK; i += BLOCK) {
            v[0] += g_partials[i * 3 + 0];
            v[1] += g_partials[i * 3 + 1];
            v[2] += g_partials[i * 3 + 2];
        }
        redN<3>(v, sh);
        if (tid == 0) {
            float obj = sh.out[0] / (float)BATCH;
            float cls = sh.out[1] / (float)BATCH;
            float loc = sh.out[2] / (float)BATCH;
            out[0] = obj; out[1] = cls; out[2] = loc;
            out[3] = obj + cls + 2.0f * loc;
            g_done = 0;  // reset for next graph replay
        }
    }
}

__global__ __launch_bounds__(BLOCK)
void loss_kernel(const float* __restrict__ pred1, const float* __restrict__ pred2,
                 const float* __restrict__ pred3,
                 const float* __restrict__ tb, const int* __restrict__ tl,
                 float* __restrict__ out)
{
    extern __shared__ unsigned char dyn[];
    __shared__ Sh sh;
    int b = blockIdx.x, scale = blockIdx.y;
    if (scale == 0)      run_scale<56>(pred1, tb, tl, out, b, 0, dyn, sh);
    else if (scale == 1) run_scale<28>(pred2, tb, tl, out, b, 1, dyn, sh);
    else                 run_scale<14>(pred3, tb, tl, out, b, 2, dyn, sh);
}

extern "C" void kernel_launch(void* const* d_in, const int* in_sizes, int n_in,
                              void* d_out, int out_size)
{
    const float* pred1 = (const float*)d_in[0];
    const float* pred2 = (const float*)d_in[1];
    const float* pred3 = (const float*)d_in[2];
    const float* tb    = (const float*)d_in[6];
    const int*   tl    = (const int*)d_in[7];

    cudaFuncSetAttribute(loss_kernel, cudaFuncAttributeMaxDynamicSharedMemorySize,
                         SMEM_BYTES);

    dim3 grid(BATCH, 3);
    loss_kernel<<<grid, BLOCK, SMEM_BYTES>>>(pred1, pred2, pred3, tb, tl, (float*)d_out);
}